// round 12
// baseline (speedup 1.0000x reference)
#include <cuda_runtime.h>
#include <cuda_bf16.h>
#include <cuda_fp16.h>
#include <math.h>
#include <stdint.h>

#define SEQ   1024
#define HEAD  64
#define HDIM  512
#define BN    8
#define NROWS (BN*SEQ)
#define EPSV  1e-5f

typedef unsigned long long u64;
typedef unsigned int u32;
typedef unsigned short u16;

// ---------------- scratch (device globals; allocation-free rule) ----------------
__device__ __align__(256) float g_sin[SEQ*32];
__device__ __align__(256) float g_cos[SEQ*32];
__device__ __align__(256) float g_scl[SEQ*32];
__device__ __align__(256) float g_Yc[NROWS*HDIM];
// fp16 operands (projection GEMMs, hi only)
__device__ __align__(256) u16 g_Xh[NROWS*HDIM];
__device__ __align__(256) u16 g_Zh[NROWS*HDIM];
__device__ __align__(256) u16 g_WgT[HDIM*HDIM];
__device__ __align__(256) u16 g_WoT[HDIM*HDIM];
__device__ __align__(256) u16 g_WqkvT[3*8*HEAD*HDIM];
// retention operands (bf16 hi/lo, pre-scaled decay+rotary+xpos)
__device__ __align__(256) u16 g_Qh[8*BN*SEQ*HEAD];
__device__ __align__(256) u16 g_Ql[8*BN*SEQ*HEAD];
__device__ __align__(256) u16 g_Kh[8*BN*SEQ*HEAD];
__device__ __align__(256) u16 g_Kl[8*BN*SEQ*HEAD];
__device__ __align__(256) u16 g_Vth[8*BN*HEAD*SEQ];
__device__ __align__(256) u16 g_Vtl[8*BN*HEAD*SEQ];

// ---------------- helpers ----------------------------------------------------------
__device__ __forceinline__ u32 smem_u32(const void* p) {
    u32 a;
    asm("{ .reg .u64 t; cvta.to.shared.u64 t, %1; cvt.u32.u64 %0, t; }" : "=r"(a) : "l"(p));
    return a;
}
__device__ __forceinline__ void ldsm_x4(u32& r0, u32& r1, u32& r2, u32& r3, u32 addr) {
    asm volatile("ldmatrix.sync.aligned.m8n8.x4.shared.b16 {%0,%1,%2,%3}, [%4];"
        : "=r"(r0), "=r"(r1), "=r"(r2), "=r"(r3) : "r"(addr));
}
__device__ __forceinline__ void mma_bf16(float* c, const u32* a, u32 b0, u32 b1) {
    asm volatile("mma.sync.aligned.m16n8k16.row.col.f32.bf16.bf16.f32 "
        "{%0,%1,%2,%3}, {%4,%5,%6,%7}, {%8,%9}, {%0,%1,%2,%3};"
        : "+f"(c[0]), "+f"(c[1]), "+f"(c[2]), "+f"(c[3])
        : "r"(a[0]), "r"(a[1]), "r"(a[2]), "r"(a[3]), "r"(b0), "r"(b1));
}
__device__ __forceinline__ void mma_f16(float* c, const u32* a, u32 b0, u32 b1) {
    asm volatile("mma.sync.aligned.m16n8k16.row.col.f32.f16.f16.f32 "
        "{%0,%1,%2,%3}, {%4,%5,%6,%7}, {%8,%9}, {%0,%1,%2,%3};"
        : "+f"(c[0]), "+f"(c[1]), "+f"(c[2]), "+f"(c[3])
        : "r"(a[0]), "r"(a[1]), "r"(a[2]), "r"(a[3]), "r"(b0), "r"(b1));
}
__device__ __forceinline__ void pack_hilo(float c0, float c1, u32& hp, u32& lp) {
    u32 h;
    asm("cvt.rn.bf16x2.f32 %0, %1, %2;" : "=r"(h) : "f"(c1), "f"(c0));
    float f0 = __uint_as_float(h << 16);
    float f1 = __uint_as_float(h & 0xffff0000u);
    asm("cvt.rn.bf16x2.f32 %0, %1, %2;" : "=r"(lp) : "f"(c1 - f1), "f"(c0 - f0));
    hp = h;
}
__device__ __forceinline__ u32 pack_f16(float c0, float c1) {
    __half2 h2 = __floats2half2_rn(c0, c1);
    return *(u32*)&h2;
}
__device__ __forceinline__ void cp16(u32 saddr, const void* g) {
    asm volatile("cp.async.cg.shared.global [%0], [%1], 16;" :: "r"(saddr), "l"(g));
}
__device__ __forceinline__ void cp_commit() {
    asm volatile("cp.async.commit_group;" ::: "memory");
}

// ---------------- xpos tables in fp64 ---------------------------------------------
__global__ void tables_kernel() {
    int idx = blockIdx.x * blockDim.x + threadIdx.x;
    if (idx >= SEQ * 32) return;
    int s = idx >> 5, j = idx & 31;
    double inv_freq = pow(10000.0, -(double)j / 32.0);
    double ang = (double)s * inv_freq;
    g_sin[idx] = (float)sin(ang);
    g_cos[idx] = (float)cos(ang);
    double sv = (2.0 * j + 25.6) / 89.6;
    g_scl[idx] = (float)pow(sv, (double)s / 512.0);
}

// ---------------- converters -------------------------------------------------------
__global__ __launch_bounds__(256) void convX_kernel(const float* __restrict__ X) {
    int i = blockIdx.x * 256 + threadIdx.x;
    float4 v = ((const float4*)X)[i];
    ((uint2*)g_Xh)[i] = make_uint2(pack_f16(v.x, v.y), pack_f16(v.z, v.w));
}
__global__ __launch_bounds__(256) void convW_all(
    const float* __restrict__ Wq, const float* __restrict__ Wk, const float* __restrict__ Wv,
    const float* __restrict__ Wg, const float* __restrict__ Wo) {
    int i = blockIdx.x * 256 + threadIdx.x;
    if (i < 524288) {
        int which = i >> 18;
        int j = i & 262143;
        int n = j >> 9, k = j & 511;
        const float* W = which ? Wo : Wg;
        u16 h = __half_as_ushort(__float2half_rn(W[(size_t)k * HDIM + n]));
        (which ? g_WoT : g_WgT)[j] = h;
    } else {
        int j = i - 524288;
        int k = j & 511, n = (j >> 9) & 63, g = (j >> 15) & 7, mat = j >> 18;
        const float* W = (mat == 0 ? Wq : (mat == 1 ? Wk : Wv));
        g_WqkvT[j] = __half_as_ushort(__float2half_rn(
            W[(size_t)g * HDIM * HEAD + (size_t)k * HEAD + n]));
    }
}

// ---------------- pure-fp16 mainloop (gate/out): K=64 chunks, 2-stage ---------------
// row pitch: 64 fp16 data + pad = 144 B (9 granules -> ldsm conflict-free)
#define RP2 144

template<int BROWS>
__device__ __forceinline__ void mma_mainloop(
    const u16* __restrict__ Ah, const u16* __restrict__ Bh, char* smem, float* C)
{
    constexpr int NTI   = BROWS / 16;
    constexpr int ABYT  = 128 * RP2;
    constexpr int BBYT  = BROWS * RP2;
    constexpr int STAGE = ABYT + BBYT;
    constexpr int AGRAN = 128 * 8;
    constexpr int BGRAN = BROWS * 8;
    constexpr int NG    = (AGRAN + BGRAN) / 256;

    int tid = threadIdx.x, lane = tid & 31, wid = tid >> 5;
    int wm = wid & 3, wn = wid >> 2;
    u32 sbase = smem_u32(smem);

    int garr[NG], grow[NG], gc[NG];
    #pragma unroll
    for (int i = 0; i < NG; i++) {
        int g = i * 256 + tid;
        int arr = (g < AGRAN) ? 0 : 1;
        int rem = (g < AGRAN) ? g : g - AGRAN;
        garr[i] = arr; grow[i] = rem >> 3; gc[i] = rem & 7;
    }
    const u16* srcs[2] = {Ah, Bh};
    const int offs[2] = {0, ABYT};

    auto issue = [&](int ch) {
        int st = ch & 1;
        int kk = ch * 64;
        #pragma unroll
        for (int i = 0; i < NG; i++)
            cp16(sbase + st*STAGE + offs[garr[i]] + grow[i]*RP2 + gc[i]*16,
                 srcs[garr[i]] + (size_t)grow[i]*HDIM + kk + gc[i]*8);
        cp_commit();
    };

    int aq = lane >> 3, ar = lane & 7;
    int a_row = wm*32 + ar + (aq & 1)*8;
    int a_kb  = (aq >> 1) * 8;
    int b_row4 = wn*(BROWS/2) + ((lane >> 4) & 1)*8 + ar;
    int b_kb4  = ((lane >> 3) & 1) * 8;

    issue(0);
    #pragma unroll 1
    for (int ch = 0; ch < 8; ch++) {
        asm volatile("cp.async.wait_group 0;" ::: "memory");
        __syncthreads();
        if (ch < 7) issue(ch + 1);
        int st = ch & 1;
        u32 sA_h = sbase + st*STAGE;
        u32 sB_h = sA_h + ABYT;
        #pragma unroll
        for (int ks = 0; ks < 4; ks++) {
            int k0 = ks * 16;
            u32 ah[2][4];
            #pragma unroll
            for (int mt = 0; mt < 2; mt++) {
                u32 ao = (u32)((a_row + mt*16) * RP2 + (k0 + a_kb) * 2);
                ldsm_x4(ah[mt][0], ah[mt][1], ah[mt][2], ah[mt][3], sA_h + ao);
            }
            #pragma unroll
            for (int ntp = 0; ntp < NTI/2; ntp++) {
                u32 bo = (u32)((b_row4 + ntp*16) * RP2 + (k0 + b_kb4) * 2);
                u32 bh[4];
                ldsm_x4(bh[0], bh[1], bh[2], bh[3], sB_h + bo);
                #pragma unroll
                for (int sub = 0; sub < 2; sub++) {
                    int nt = ntp*2 + sub;
                    #pragma unroll
                    for (int mt = 0; mt < 2; mt++)
                        mma_f16(C + (mt*NTI + nt)*4, ah[mt], bh[sub*2], bh[sub*2+1]);
                }
            }
        }
    }
}

// ---------------- QKV GEMM (merged NT=192, fp16, K=64 chunks) -----------------------
// stage 46080 B: A@0 (18432), B@18432 (27648). 2 stages = 92160.
__global__ __launch_bounds__(256, 2) void qkv_mma_kernel() {
    extern __shared__ __align__(128) char smem[];
    const int ABYT = 18432, STAGE = 46080;
    const int offs[2] = {0, ABYT};
    u32 sbase = smem_u32(smem);

    int tid = threadIdx.x, lane = tid & 31, wid = tid >> 5;
    int wm = wid & 3, wn = wid >> 2;
    int g4 = lane >> 2, t4 = lane & 3;
    int rowTile = blockIdx.x * 128;
    int g = blockIdx.y;

    const u16* Ah = g_Xh + (size_t)rowTile*HDIM;
    const u16* srcs[2] = {Ah, g_WqkvT};

    // 2560 granules: A 1024, B 1536 -> 10 per thread
    int garr[10], grow[10], gc[10], gsrow[10];
    #pragma unroll
    for (int i = 0; i < 10; i++) {
        int gg = i * 256 + tid;
        int arr = (gg < 1024) ? 0 : 1;
        int rem = (gg < 1024) ? gg : gg - 1024;
        garr[i] = arr; grow[i] = rem >> 3; gc[i] = rem & 7;
        gsrow[i] = (arr == 0) ? grow[i] : ((grow[i] >> 6)*512 + g*64 + (grow[i] & 63));
    }
    auto issue = [&](int ch) {
        int st = ch & 1;
        u32 db = sbase + st*STAGE;
        int kk = ch * 64;
        #pragma unroll
        for (int i = 0; i < 10; i++)
            cp16(db + offs[garr[i]] + grow[i]*RP2 + gc[i]*16,
                 srcs[garr[i]] + (size_t)gsrow[i]*HDIM + kk + gc[i]*8);
        cp_commit();
    };

    int aq = lane >> 3, ar = lane & 7;
    int a_row = wm*32 + ar + (aq & 1)*8;
    int a_kb  = (aq >> 1) * 8;
    int b_row4 = wn*96 + ((lane >> 4) & 1)*8 + ar;
    int b_kb4  = ((lane >> 3) & 1) * 8;

    float C[2*12*4] = {};

    issue(0);
    #pragma unroll 1
    for (int ch = 0; ch < 8; ch++) {
        asm volatile("cp.async.wait_group 0;" ::: "memory");
        __syncthreads();
        if (ch < 7) issue(ch + 1);
        int st = ch & 1;
        u32 sA_h = sbase + st*STAGE;
        u32 sB_h = sA_h + ABYT;
        #pragma unroll
        for (int ks = 0; ks < 4; ks++) {
            int k0 = ks * 16;
            u32 ah[2][4];
            #pragma unroll
            for (int mt = 0; mt < 2; mt++) {
                u32 ao = (u32)((a_row + mt*16) * RP2 + (k0 + a_kb) * 2);
                ldsm_x4(ah[mt][0], ah[mt][1], ah[mt][2], ah[mt][3], sA_h + ao);
            }
            #pragma unroll
            for (int ntp = 0; ntp < 6; ntp++) {
                u32 bo = (u32)((b_row4 + ntp*16) * RP2 + (k0 + b_kb4) * 2);
                u32 bh[4];
                ldsm_x4(bh[0], bh[1], bh[2], bh[3], sB_h + bo);
                #pragma unroll
                for (int sub = 0; sub < 2; sub++) {
                    int nt = ntp*2 + sub;
                    #pragma unroll
                    for (int mt = 0; mt < 2; mt++)
                        mma_f16(C + (mt*12 + nt)*4, ah[mt], bh[sub*2], bh[sub*2+1]);
                }
            }
        }
    }

    // ---- epilogue ----
    int bn = rowTile >> 10, sb = rowTile & 1023;
    size_t gbn = (size_t)(g*8 + bn);

    double lgd = log(1.0/32.0) + (double)g * ((log(1.0/512.0) - log(1.0/32.0)) / 7.0);
    float log2g = (float)log2(1.0 - exp(lgd));
    float fdq[2][2], fdk[2][2];
    #pragma unroll
    for (int mt = 0; mt < 2; mt++)
        #pragma unroll
        for (int h = 0; h < 2; h++) {
            float sidx = (float)(sb + wm*32 + mt*16 + g4 + h*8);
            fdq[mt][h] = exp2f(sidx * log2g);
            fdk[mt][h] = exp2f(-sidx * log2g);
        }

    __syncthreads();
    u16* sVh = (u16*)smem;       // [64][136]
    u16* sVl = (u16*)smem + 64*136;

    #pragma unroll
    for (int nt = 0; nt < 12; nt++) {
        int col192 = wn*96 + nt*8 + t4*2;
        int mat = col192 >> 6, col = col192 & 63;
        #pragma unroll
        for (int mt = 0; mt < 2; mt++) {
            const float* c = C + (mt*12 + nt)*4;
            #pragma unroll
            for (int h = 0; h < 2; h++) {
                int rloc = wm*32 + mt*16 + g4 + h*8;
                int s = sb + rloc;
                float e = c[h*2], o = c[h*2 + 1];
                if (mat == 2) {
                    u32 hp, lp;
                    pack_hilo(e, o, hp, lp);           // V stays bf16 hi/lo
                    sVh[col*136 + rloc]     = (u16)(hp & 0xffffu);
                    sVh[(col+1)*136 + rloc] = (u16)(hp >> 16);
                    sVl[col*136 + rloc]     = (u16)(lp & 0xffffu);
                    sVl[(col+1)*136 + rloc] = (u16)(lp >> 16);
                } else {
                    int j2 = col >> 1;
                    float sn = g_sin[s*32 + j2], cs = g_cos[s*32 + j2], sc = g_scl[s*32 + j2];
                    float re = e*cs - o*sn;
                    float ro = o*cs + e*sn;
                    float m = (mat == 0) ? sc * fdq[mt][h] : (1.0f/sc) * fdk[mt][h];
                    u32 hp, lp;
                    pack_hilo(re*m, ro*m, hp, lp);     // Q/K stay bf16 hi/lo
                    size_t off = (gbn*SEQ + s)*HEAD + col;
                    if (mat == 0) { *(u32*)&g_Qh[off] = hp; *(u32*)&g_Ql[off] = lp; }
                    else          { *(u32*)&g_Kh[off] = hp; *(u32*)&g_Kl[off] = lp; }
                }
            }
        }
    }
    __syncthreads();
    #pragma unroll
    for (int p = 0; p < 4; p++) {
        int lin = p*256 + tid;
        int d = lin >> 4, c16 = lin & 15;
        *(uint4*)&g_Vth[(gbn*HEAD + d)*SEQ + sb + c16*8] = *(const uint4*)&sVh[d*136 + c16*8];
        *(uint4*)&g_Vtl[(gbn*HEAD + d)*SEQ + sb + c16*8] = *(const uint4*)&sVl[d*136 + c16*8];
    }
}

// ---------------- gate GEMM: Z = silu(X@Wg)*Yc -> fp16 ------------------------------
__global__ __launch_bounds__(256, 2) void gate_mma_kernel() {
    extern __shared__ __align__(128) char smem[];
    int rowTile = blockIdx.x * 128, ct = blockIdx.y * 128;

    float C[2*8*4] = {};
    mma_mainloop<128>(g_Xh + (size_t)rowTile*HDIM, g_WgT + (size_t)ct*HDIM, smem, C);

    int tid = threadIdx.x, lane = tid & 31, wid = tid >> 5;
    int wm = wid & 3, wn = wid >> 2, g4 = lane >> 2, t4 = lane & 3;

    #pragma unroll
    for (int mt = 0; mt < 2; mt++)
        #pragma unroll
        for (int nt = 0; nt < 8; nt++) {
            const float* c = C + (mt*8 + nt)*4;
            int col = ct + wn*64 + nt*8 + t4*2;
            #pragma unroll
            for (int h = 0; h < 2; h++) {
                int row = rowTile + wm*32 + mt*16 + g4 + h*8;
                size_t off = (size_t)row*HDIM + col;
                float2 y = *(const float2*)&g_Yc[off];
                float v0 = c[h*2], v1 = c[h*2 + 1];
                float z0 = v0 / (1.0f + expf(-v0)) * y.x;
                float z1 = v1 / (1.0f + expf(-v1)) * y.y;
                *(u32*)&g_Zh[off] = pack_f16(z0, z1);
            }
        }
}

// ---------------- output GEMM: out = Z @ Wo ------------------------------------------
__global__ __launch_bounds__(256, 2) void out_mma_kernel(float* __restrict__ out) {
    extern __shared__ __align__(128) char smem[];
    int rowTile = blockIdx.x * 128, ct = blockIdx.y * 128;

    float C[2*8*4] = {};
    mma_mainloop<128>(g_Zh + (size_t)rowTile*HDIM, g_WoT + (size_t)ct*HDIM, smem, C);

    int tid = threadIdx.x, lane = tid & 31, wid = tid >> 5;
    int wm = wid & 3, wn = wid >> 2, g4 = lane >> 2, t4 = lane & 3;

    #pragma unroll
    for (int mt = 0; mt < 2; mt++)
        #pragma unroll
        for (int nt = 0; nt < 8; nt++) {
            const float* c = C + (mt*8 + nt)*4;
            int col = ct + wn*64 + nt*8 + t4*2;
            #pragma unroll
            for (int h = 0; h < 2; h++) {
                int row = rowTile + wm*32 + mt*16 + g4 + h*8;
                *(float2*)&out[(size_t)row*HDIM + col] = make_float2(c[h*2], c[h*2 + 1]);
            }
        }
}

// ---------------- retention (bf16x3, register S, cp.async 2-stage, mask-skip) -------
__global__ __launch_bounds__(256, 2) void ret_mma_kernel(
    const float* __restrict__ gnw, const float* __restrict__ gnb)
{
    extern __shared__ __align__(128) char smem[];
    const int QH = 0, QL = 18432, STG = 36864, SSZ = 36864;
    const int KHo = 0, KLo = 9216, VHo = 18432, VLo = 27648;
    u32 sbase = smem_u32(smem);

    int tid = threadIdx.x, lane = tid & 31, wid = tid >> 5;
    int wm = wid & 3, wn = wid >> 2;
    int g4 = lane >> 2, t4 = lane & 3;
    int bx = 7 - (int)blockIdx.x;
    int gbn = blockIdx.y, g = gbn >> 3, bn = gbn & 7;
    int s0 = bx * 128;

    const u16* Qh = g_Qh + ((size_t)gbn*SEQ + s0)*HEAD;
    const u16* Ql = g_Ql + ((size_t)gbn*SEQ + s0)*HEAD;
    const u16* Kh = g_Kh + (size_t)gbn*SEQ*HEAD;
    const u16* Kl = g_Kl + (size_t)gbn*SEQ*HEAD;
    const u16* Vh = g_Vth + (size_t)gbn*HEAD*SEQ;
    const u16* Vl = g_Vtl + (size_t)gbn*HEAD*SEQ;

    #pragma unroll
    for (int p = 0; p < 4; p++) {
        int lin = p*256 + tid;
        int r = lin >> 3, c16 = lin & 7;
        cp16(sbase + QH + r*144 + c16*16, Qh + (size_t)r*HEAD + c16*8);
        cp16(sbase + QL + r*144 + c16*16, Ql + (size_t)r*HEAD + c16*8);
    }

    auto load_tile = [&](int jt) {
        int t0 = jt * 64;
        u32 sb2 = sbase + STG + (jt & 1)*SSZ;
        #pragma unroll
        for (int p = 0; p < 2; p++) {
            int lin = p*256 + tid;
            int r = lin >> 3, c16 = lin & 7;
            cp16(sb2 + KHo + r*144 + c16*16, Kh + (size_t)(t0 + r)*HEAD + c16*8);
            cp16(sb2 + KLo + r*144 + c16*16, Kl + (size_t)(t0 + r)*HEAD + c16*8);
            cp16(sb2 + VHo + r*144 + c16*16, Vh + (size_t)r*SEQ + t0 + c16*8);
            cp16(sb2 + VLo + r*144 + c16*16, Vl + (size_t)r*SEQ + t0 + c16*8);
        }
        cp_commit();
    };
    load_tile(0);

    int aq = lane >> 3, ar = lane & 7;
    int a_row = wm*32 + ar + (aq & 1)*8;
    int a_kb  = (aq >> 1) * 8;
    int brow4 = ((lane >> 4) & 1)*8 + ar;
    int b_kb4 = ((lane >> 3) & 1) * 8;

    float accY[2*8*4] = {};
    int jtmax = 2*bx + 1;
    for (int jt = 0; jt <= jtmax; jt++) {
        int t0 = jt * 64;
        asm volatile("cp.async.wait_group 0;" ::: "memory");
        __syncthreads();
        if (jt < jtmax) load_tile(jt + 1);

        u32 stg = sbase + STG + (jt & 1)*SSZ;
        u32 sK_h = stg + KHo, sK_l = stg + KLo;
        u32 sV_h = stg + VHo, sV_l = stg + VLo;
        bool diag = (jt >= 2*bx);

        #pragma unroll
        for (int kt = 0; kt < 2; kt++) {
            if (diag && (t0 + wn*32 + kt*16) > (s0 + wm*32 + 31)) continue;

            float accS[2][2][4] = {};
            #pragma unroll
            for (int ks = 0; ks < 4; ks++) {
                int k0 = ks * 16;
                u32 ah[2][4], al[2][4];
                #pragma unroll
                for (int mt = 0; mt < 2; mt++) {
                    u32 ao = (u32)((a_row + mt*16)*144 + (k0 + a_kb)*2);
                    ldsm_x4(ah[mt][0], ah[mt][1], ah[mt][2], ah[mt][3], sbase + QH + ao);
                    ldsm_x4(al[mt][0], al[mt][1], al[mt][2], al[mt][3], sbase + QL + ao);
                }
                u32 bo = (u32)((wn*32 + kt*16 + brow4)*144 + (k0 + b_kb4)*2);
                u32 bh[4], bl[4];
                ldsm_x4(bh[0], bh[1], bh[2], bh[3], sK_h + bo);
                ldsm_x4(bl[0], bl[1], bl[2], bl[3], sK_l + bo);
                #pragma unroll
                for (int ntp = 0; ntp < 2; ntp++)
                    #pragma unroll
                    for (int mt = 0; mt < 2; mt++) {
                        float* c = accS[mt][ntp];
                        mma_bf16(c, ah[mt], bh[ntp*2], bh[ntp*2+1]);
                        mma_bf16(c, ah[mt], bl[ntp*2], bl[ntp*2+1]);
                        mma_bf16(c, al[mt], bh[ntp*2], bh[ntp*2+1]);
                    }
            }
            u32 sa_h[2][4], sa_l[2][4];
            #pragma unroll
            for (int mt = 0; mt < 2; mt++) {
                #pragma unroll
                for (int ntp = 0; ntp < 2; ntp++) {
                    float* c = accS[mt][ntp];
                    if (diag) {
                        int tb = t0 + wn*32 + kt*16 + ntp*8 + t4*2;
                        int sg0 = s0 + wm*32 + mt*16 + g4;
                        if (tb     > sg0)     c[0] = 0.f;
                        if (tb + 1 > sg0)     c[1] = 0.f;
                        if (tb     > sg0 + 8) c[2] = 0.f;
                        if (tb + 1 > sg0 + 8) c[3] = 0.f;
                    }
                    pack_hilo(c[0], c[1], sa_h[mt][ntp*2],     sa_l[mt][ntp*2]);
                    pack_hilo(c[2], c[3], sa_h[mt][ntp*2 + 1], sa_l[mt][ntp*2 + 1]);
                }
            }
            #pragma unroll
            for (int ntp2 = 0; ntp2 < 4; ntp2++) {
                u32 bo = (u32)((ntp2*16 + brow4)*144 + (wn*32 + kt*16 + b_kb4)*2);
                u32 bh[4], bl[4];
                ldsm_x4(bh[0], bh[1], bh[2], bh[3], sV_h + bo);
                ldsm_x4(bl[0], bl[1], bl[2], bl[3], sV_l + bo);
                #pragma unroll
                for (int sub = 0; sub < 2; sub++) {
                    int nt2 = ntp2*2 + sub;
                    #pragma unroll
                    for (int mt = 0; mt < 2; mt++) {
                        float* c = accY + (mt*8 + nt2)*4;
                        mma_bf16(c, sa_h[mt], bh[sub*2], bh[sub*2+1]);
                        mma_bf16(c, sa_h[mt], bl[sub*2], bl[sub*2+1]);
                        mma_bf16(c, sa_l[mt], bh[sub*2], bh[sub*2+1]);
                    }
                }
            }
        }
    }

    // cross-warp (wn) Y reduction + group-norm
    __syncthreads();
    float* stage = (float*)smem;   // [128][68]
    if (wn == 0) {
        #pragma unroll
        for (int mt = 0; mt < 2; mt++)
            #pragma unroll
            for (int nt2 = 0; nt2 < 8; nt2++) {
                const float* c = accY + (mt*8 + nt2)*4;
                int col = nt2*8 + t4*2;
                #pragma unroll
                for (int h = 0; h < 2; h++) {
                    int rloc = wm*32 + mt*16 + g4 + h*8;
                    *(float2*)&stage[rloc*68 + col] = make_float2(c[h*2], c[h*2 + 1]);
                }
            }
    }
    __syncthreads();
    if (wn == 1) {
        #pragma unroll
        for (int mt = 0; mt < 2; mt++)
            #pragma unroll
            for (int nt2 = 0; nt2 < 8; nt2++) {
                const float* c = accY + (mt*8 + nt2)*4;
                int col = nt2*8 + t4*2;
                #pragma unroll
                for (int h = 0; h < 2; h++) {
                    int rloc = wm*32 + mt*16 + g4 + h*8;
                    float2 v = *(const float2*)&stage[rloc*68 + col];
                    v.x += c[h*2]; v.y += c[h*2 + 1];
                    *(float2*)&stage[rloc*68 + col] = v;
                }
            }
    }
    __syncthreads();

    float w0 = gnw[g*64 + lane], w1 = gnw[g*64 + lane + 32];
    float b0 = gnb[g*64 + lane], b1 = gnb[g*64 + lane + 32];
    for (int rr = 0; rr < 16; rr++) {
        int row = wid*16 + rr;
        float v0 = stage[row*68 + lane], v1 = stage[row*68 + lane + 32];
        float sum = v0 + v1;
        #pragma unroll
        for (int off = 16; off; off >>= 1) sum += __shfl_xor_sync(0xffffffffu, sum, off);
        float mean = sum * 0.015625f;
        float d0 = v0 - mean, d1 = v1 - mean;
        float sq = d0*d0 + d1*d1;
        #pragma unroll
        for (int off = 16; off; off >>= 1) sq += __shfl_xor_sync(0xffffffffu, sq, off);
        float rstd = rsqrtf(sq * 0.015625f + EPSV);
        float* dst = g_Yc + ((size_t)(bn*SEQ + s0 + row))*HDIM + g*64;
        dst[lane]      = d0 * rstd * w0 + b0;
        dst[lane + 32] = d1 * rstd * w1 + b1;
    }
}

// ---------------- launch -------------------------------------------------------------
extern "C" void kernel_launch(void* const* d_in, const int* in_sizes, int n_in,
                              void* d_out, int out_size)
{
    (void)in_sizes; (void)n_in; (void)out_size;
    const float* X   = (const float*)d_in[0];
    const float* Wq  = (const float*)d_in[1];
    const float* Wk  = (const float*)d_in[2];
    const float* Wv  = (const float*)d_in[3];
    const float* Wg  = (const float*)d_in[4];
    const float* Wo  = (const float*)d_in[5];
    const float* gnw = (const float*)d_in[6];
    const float* gnb = (const float*)d_in[7];
    float* out = (float*)d_out;

    const int RET_SMEM  = 36864 + 2*36864;   // 110592
    const int SMEM_QKV  = 2 * 46080;         //  92160
    const int SMEM_128  = 2 * 36864;         //  73728
    cudaFuncSetAttribute(ret_mma_kernel, cudaFuncAttributeMaxDynamicSharedMemorySize, RET_SMEM);
    cudaFuncSetAttribute(qkv_mma_kernel, cudaFuncAttributeMaxDynamicSharedMemorySize, SMEM_QKV);
    cudaFuncSetAttribute(gate_mma_kernel, cudaFuncAttributeMaxDynamicSharedMemorySize, SMEM_128);
    cudaFuncSetAttribute(out_mma_kernel, cudaFuncAttributeMaxDynamicSharedMemorySize, SMEM_128);

    tables_kernel<<<128, 256>>>();
    convX_kernel<<<NROWS*HDIM/4/256, 256>>>(X);
    convW_all<<<5120, 256>>>(Wq, Wk, Wv, Wg, Wo);
    qkv_mma_kernel<<<dim3(64, 8), 256, SMEM_QKV>>>();
    ret_mma_kernel<<<dim3(8, 64), 256, RET_SMEM>>>(gnw, gnb);
    gate_mma_kernel<<<dim3(64, 4), 256, SMEM_128>>>();
    out_mma_kernel<<<dim3(64, 4), 256, SMEM_128>>>(out);
}

// round 13
// speedup vs baseline: 1.0618x; 1.0618x over previous
#include <cuda_runtime.h>
#include <cuda_bf16.h>
#include <cuda_fp16.h>
#include <math.h>
#include <stdint.h>

#define SEQ   1024
#define HEAD  64
#define HDIM  512
#define BN    8
#define NROWS (BN*SEQ)
#define EPSV  1e-5f

typedef unsigned long long u64;
typedef unsigned int u32;
typedef unsigned short u16;

// ---------------- scratch (device globals; allocation-free rule) ----------------
__device__ __align__(256) float g_sin[SEQ*32];
__device__ __align__(256) float g_cos[SEQ*32];
__device__ __align__(256) float g_scl[SEQ*32];
__device__ __align__(256) float g_Yc[NROWS*HDIM];
// fp16 operands (projection GEMMs, hi only)
__device__ __align__(256) u16 g_Xh[NROWS*HDIM];
__device__ __align__(256) u16 g_Zh[NROWS*HDIM];
__device__ __align__(256) u16 g_WgT[HDIM*HDIM];
__device__ __align__(256) u16 g_WoT[HDIM*HDIM];
__device__ __align__(256) u16 g_WqkvT[3*8*HEAD*HDIM];
// retention operands, fp16, tile-local decay fold:
//   Q' = Q rot sc  γ^(s mod 128)   (hi/lo)
//   K' = K rot /sc γ^-(t mod 64)   (hi only)
//   V  transposed [d][t]           (hi only)
__device__ __align__(256) u16 g_Qh[8*BN*SEQ*HEAD];
__device__ __align__(256) u16 g_Ql[8*BN*SEQ*HEAD];
__device__ __align__(256) u16 g_Kh[8*BN*SEQ*HEAD];
__device__ __align__(256) u16 g_Vth[8*BN*HEAD*SEQ];

// ---------------- helpers ----------------------------------------------------------
__device__ __forceinline__ u32 smem_u32(const void* p) {
    u32 a;
    asm("{ .reg .u64 t; cvta.to.shared.u64 t, %1; cvt.u32.u64 %0, t; }" : "=r"(a) : "l"(p));
    return a;
}
__device__ __forceinline__ void ldsm_x4(u32& r0, u32& r1, u32& r2, u32& r3, u32 addr) {
    asm volatile("ldmatrix.sync.aligned.m8n8.x4.shared.b16 {%0,%1,%2,%3}, [%4];"
        : "=r"(r0), "=r"(r1), "=r"(r2), "=r"(r3) : "r"(addr));
}
__device__ __forceinline__ void mma_f16(float* c, const u32* a, u32 b0, u32 b1) {
    asm volatile("mma.sync.aligned.m16n8k16.row.col.f32.f16.f16.f32 "
        "{%0,%1,%2,%3}, {%4,%5,%6,%7}, {%8,%9}, {%0,%1,%2,%3};"
        : "+f"(c[0]), "+f"(c[1]), "+f"(c[2]), "+f"(c[3])
        : "r"(a[0]), "r"(a[1]), "r"(a[2]), "r"(a[3]), "r"(b0), "r"(b1));
}
__device__ __forceinline__ u32 pack_f16(float c0, float c1) {
    __half2 h2 = __floats2half2_rn(c0, c1);
    return *(u32*)&h2;
}
__device__ __forceinline__ void pack_hilo_f16(float c0, float c1, u32& hp, u32& lp) {
    __half2 h2 = __floats2half2_rn(c0, c1);
    float2 hf = __half22float2(h2);
    __half2 l2 = __floats2half2_rn(c0 - hf.x, c1 - hf.y);
    hp = *(u32*)&h2;
    lp = *(u32*)&l2;
}
__device__ __forceinline__ void cp16(u32 saddr, const void* g) {
    asm volatile("cp.async.cg.shared.global [%0], [%1], 16;" :: "r"(saddr), "l"(g));
}
__device__ __forceinline__ void cp_commit() {
    asm volatile("cp.async.commit_group;" ::: "memory");
}

// ---------------- xpos tables in fp64 ---------------------------------------------
__global__ void tables_kernel() {
    int idx = blockIdx.x * blockDim.x + threadIdx.x;
    if (idx >= SEQ * 32) return;
    int s = idx >> 5, j = idx & 31;
    double inv_freq = pow(10000.0, -(double)j / 32.0);
    double ang = (double)s * inv_freq;
    g_sin[idx] = (float)sin(ang);
    g_cos[idx] = (float)cos(ang);
    double sv = (2.0 * j + 25.6) / 89.6;
    g_scl[idx] = (float)pow(sv, (double)s / 512.0);
}

// ---------------- converters -------------------------------------------------------
__global__ __launch_bounds__(256) void convX_kernel(const float* __restrict__ X) {
    int i = blockIdx.x * 256 + threadIdx.x;
    float4 v = ((const float4*)X)[i];
    ((uint2*)g_Xh)[i] = make_uint2(pack_f16(v.x, v.y), pack_f16(v.z, v.w));
}
__global__ __launch_bounds__(256) void convW_all(
    const float* __restrict__ Wq, const float* __restrict__ Wk, const float* __restrict__ Wv,
    const float* __restrict__ Wg, const float* __restrict__ Wo) {
    int i = blockIdx.x * 256 + threadIdx.x;
    if (i < 524288) {
        int which = i >> 18;
        int j = i & 262143;
        int n = j >> 9, k = j & 511;
        const float* W = which ? Wo : Wg;
        u16 h = __half_as_ushort(__float2half_rn(W[(size_t)k * HDIM + n]));
        (which ? g_WoT : g_WgT)[j] = h;
    } else {
        int j = i - 524288;
        int k = j & 511, n = (j >> 9) & 63, g = (j >> 15) & 7, mat = j >> 18;
        const float* W = (mat == 0 ? Wq : (mat == 1 ? Wk : Wv));
        g_WqkvT[j] = __half_as_ushort(__float2half_rn(
            W[(size_t)g * HDIM * HEAD + (size_t)k * HEAD + n]));
    }
}

// ---------------- pure-fp16 mainloop (gate/out): cp.async 2-stage, K=32 -------------
#define PITCH 40

template<int BROWS>
__device__ __forceinline__ void mma_mainloop(
    const u16* __restrict__ Ah, const u16* __restrict__ Bh, char* smem, float* C)
{
    constexpr int NTI   = BROWS / 16;
    constexpr int ABYT  = 128 * PITCH * 2;
    constexpr int BBYT  = BROWS * PITCH * 2;
    constexpr int STAGE = ABYT + BBYT;
    constexpr int AGRAN = 128 * 4;
    constexpr int BGRAN = BROWS * 4;
    constexpr int NG    = (AGRAN + BGRAN) / 256;

    int tid = threadIdx.x, lane = tid & 31, wid = tid >> 5;
    int wm = wid & 3, wn = wid >> 2;
    u32 sbase = smem_u32(smem);

    int garr[NG], grow[NG], gc16[NG];
    #pragma unroll
    for (int i = 0; i < NG; i++) {
        int g = i * 256 + tid;
        int arr = (g < AGRAN) ? 0 : 1;
        int rem = (g < AGRAN) ? g : g - AGRAN;
        garr[i] = arr; grow[i] = rem >> 2; gc16[i] = rem & 3;
    }
    const u16* srcs[2] = {Ah, Bh};
    const int offs[2] = {0, ABYT};

    auto issue = [&](int ch) {
        int st = ch & 1;
        int kk = ch * 32;
        #pragma unroll
        for (int i = 0; i < NG; i++)
            cp16(sbase + st*STAGE + offs[garr[i]] + grow[i]*(PITCH*2) + gc16[i]*16,
                 srcs[garr[i]] + (size_t)grow[i]*HDIM + kk + gc16[i]*8);
        cp_commit();
    };

    int aq = lane >> 3, ar = lane & 7;
    int a_row = wm*32 + ar + (aq & 1)*8;
    int a_kb  = (aq >> 1) * 8;
    int b_row4 = wn*(BROWS/2) + ((lane >> 4) & 1)*8 + ar;
    int b_kb4  = ((lane >> 3) & 1) * 8;

    issue(0);
    #pragma unroll 1
    for (int ch = 0; ch < 16; ch++) {
        asm volatile("cp.async.wait_group 0;" ::: "memory");
        __syncthreads();
        if (ch < 15) issue(ch + 1);
        int st = ch & 1;
        u32 sA_h = sbase + st*STAGE;
        u32 sB_h = sA_h + ABYT;
        #pragma unroll
        for (int ks = 0; ks < 2; ks++) {
            int k0 = ks * 16;
            u32 ah[2][4];
            #pragma unroll
            for (int mt = 0; mt < 2; mt++) {
                u32 ao = (u32)((a_row + mt*16) * (PITCH*2) + (k0 + a_kb) * 2);
                ldsm_x4(ah[mt][0], ah[mt][1], ah[mt][2], ah[mt][3], sA_h + ao);
            }
            #pragma unroll
            for (int ntp = 0; ntp < NTI/2; ntp++) {
                u32 bo = (u32)((b_row4 + ntp*16) * (PITCH*2) + (k0 + b_kb4) * 2);
                u32 bh[4];
                ldsm_x4(bh[0], bh[1], bh[2], bh[3], sB_h + bo);
                #pragma unroll
                for (int sub = 0; sub < 2; sub++) {
                    int nt = ntp*2 + sub;
                    #pragma unroll
                    for (int mt = 0; mt < 2; mt++)
                        mma_f16(C + (mt*NTI + nt)*4, ah[mt], bh[sub*2], bh[sub*2+1]);
                }
            }
        }
    }
}

// ---------------- QKV GEMM (merged NT=192, pure fp16, K=32, 2-stage) ----------------
__global__ __launch_bounds__(256, 2) void qkv_mma_kernel() {
    extern __shared__ __align__(128) char smem[];
    const int ABYT = 10240, STAGE = 25600;
    const int offs[2] = {0, ABYT};
    u32 sbase = smem_u32(smem);

    int tid = threadIdx.x, lane = tid & 31, wid = tid >> 5;
    int wm = wid & 3, wn = wid >> 2;
    int g4 = lane >> 2, t4 = lane & 3;
    int rowTile = blockIdx.x * 128;
    int g = blockIdx.y;

    const u16* Ah = g_Xh + (size_t)rowTile*HDIM;
    const u16* srcs[2] = {Ah, g_WqkvT};

    int garr[5], grow[5], gc16[5], gsrow[5];
    #pragma unroll
    for (int i = 0; i < 5; i++) {
        int gg = i * 256 + tid;
        int arr = (gg < 512) ? 0 : 1;
        int rem = (gg < 512) ? gg : gg - 512;
        garr[i] = arr; grow[i] = rem >> 2; gc16[i] = rem & 3;
        gsrow[i] = (arr == 0) ? grow[i] : ((grow[i] >> 6)*512 + g*64 + (grow[i] & 63));
    }
    auto issue = [&](int ch) {
        int st = ch & 1;
        u32 db = sbase + st*STAGE;
        int kk = ch * 32;
        #pragma unroll
        for (int i = 0; i < 5; i++)
            cp16(db + offs[garr[i]] + grow[i]*(PITCH*2) + gc16[i]*16,
                 srcs[garr[i]] + (size_t)gsrow[i]*HDIM + kk + gc16[i]*8);
        cp_commit();
    };

    int aq = lane >> 3, ar = lane & 7;
    int a_row = wm*32 + ar + (aq & 1)*8;
    int a_kb  = (aq >> 1) * 8;
    int b_row4 = wn*96 + ((lane >> 4) & 1)*8 + ar;
    int b_kb4  = ((lane >> 3) & 1) * 8;

    float C[2*12*4] = {};

    issue(0);
    #pragma unroll 1
    for (int ch = 0; ch < 16; ch++) {
        asm volatile("cp.async.wait_group 0;" ::: "memory");
        __syncthreads();
        if (ch < 15) issue(ch + 1);
        int st = ch & 1;
        u32 sA_h = sbase + st*STAGE;
        u32 sB_h = sA_h + ABYT;
        #pragma unroll
        for (int ks = 0; ks < 2; ks++) {
            int k0 = ks * 16;
            u32 ah[2][4];
            #pragma unroll
            for (int mt = 0; mt < 2; mt++) {
                u32 ao = (u32)((a_row + mt*16) * (PITCH*2) + (k0 + a_kb) * 2);
                ldsm_x4(ah[mt][0], ah[mt][1], ah[mt][2], ah[mt][3], sA_h + ao);
            }
            #pragma unroll
            for (int ntp = 0; ntp < 6; ntp++) {
                u32 bo = (u32)((b_row4 + ntp*16) * (PITCH*2) + (k0 + b_kb4) * 2);
                u32 bh[4];
                ldsm_x4(bh[0], bh[1], bh[2], bh[3], sB_h + bo);
                #pragma unroll
                for (int sub = 0; sub < 2; sub++) {
                    int nt = ntp*2 + sub;
                    #pragma unroll
                    for (int mt = 0; mt < 2; mt++)
                        mma_f16(C + (mt*12 + nt)*4, ah[mt], bh[sub*2], bh[sub*2+1]);
                }
            }
        }
    }

    // ---- epilogue: rotary/xpos + TILE-LOCAL decay fold, fp16 outputs ----
    int bn = rowTile >> 10, sb = rowTile & 1023;   // sb is 128-aligned
    size_t gbn = (size_t)(g*8 + bn);

    double lgd = log(1.0/32.0) + (double)g * ((log(1.0/512.0) - log(1.0/32.0)) / 7.0);
    float log2g = (float)log2(1.0 - exp(lgd));
    float fdq[2][2], fdk[2][2];
    #pragma unroll
    for (int mt = 0; mt < 2; mt++)
        #pragma unroll
        for (int h = 0; h < 2; h++) {
            int rloc = wm*32 + mt*16 + g4 + h*8;
            fdq[mt][h] = exp2f((float)rloc * log2g);          // gamma^(s mod 128)
            fdk[mt][h] = exp2f(-(float)(rloc & 63) * log2g);  // gamma^-(t mod 64)
        }

    __syncthreads();
    u16* sVh = (u16*)smem;       // [64][136]

    #pragma unroll
    for (int nt = 0; nt < 12; nt++) {
        int col192 = wn*96 + nt*8 + t4*2;
        int mat = col192 >> 6, col = col192 & 63;
        #pragma unroll
        for (int mt = 0; mt < 2; mt++) {
            const float* c = C + (mt*12 + nt)*4;
            #pragma unroll
            for (int h = 0; h < 2; h++) {
                int rloc = wm*32 + mt*16 + g4 + h*8;
                int s = sb + rloc;
                float e = c[h*2], o = c[h*2 + 1];
                if (mat == 2) {
                    sVh[col*136 + rloc]     = __half_as_ushort(__float2half_rn(e));
                    sVh[(col+1)*136 + rloc] = __half_as_ushort(__float2half_rn(o));
                } else {
                    int j2 = col >> 1;
                    float sn = g_sin[s*32 + j2], cs = g_cos[s*32 + j2], sc = g_scl[s*32 + j2];
                    float re = e*cs - o*sn;
                    float ro = o*cs + e*sn;
                    size_t off = (gbn*SEQ + s)*HEAD + col;
                    if (mat == 0) {
                        float m = sc * fdq[mt][h];
                        u32 hp, lp;
                        pack_hilo_f16(re*m, ro*m, hp, lp);
                        *(u32*)&g_Qh[off] = hp;
                        *(u32*)&g_Ql[off] = lp;
                    } else {
                        float m = (1.0f/sc) * fdk[mt][h];
                        *(u32*)&g_Kh[off] = pack_f16(re*m, ro*m);
                    }
                }
            }
        }
    }
    __syncthreads();
    #pragma unroll
    for (int p = 0; p < 4; p++) {
        int lin = p*256 + tid;
        int d = lin >> 4, c16 = lin & 15;
        *(uint4*)&g_Vth[(gbn*HEAD + d)*SEQ + sb + c16*8] = *(const uint4*)&sVh[d*136 + c16*8];
    }
}

// ---------------- gate GEMM: Z = silu(X@Wg)*Yc -> fp16 ------------------------------
__global__ __launch_bounds__(256, 2) void gate_mma_kernel() {
    extern __shared__ __align__(128) char smem[];
    int rowTile = blockIdx.x * 128, ct = blockIdx.y * 128;

    float C[2*8*4] = {};
    mma_mainloop<128>(g_Xh + (size_t)rowTile*HDIM, g_WgT + (size_t)ct*HDIM, smem, C);

    int tid = threadIdx.x, lane = tid & 31, wid = tid >> 5;
    int wm = wid & 3, wn = wid >> 2, g4 = lane >> 2, t4 = lane & 3;

    #pragma unroll
    for (int mt = 0; mt < 2; mt++)
        #pragma unroll
        for (int nt = 0; nt < 8; nt++) {
            const float* c = C + (mt*8 + nt)*4;
            int col = ct + wn*64 + nt*8 + t4*2;
            #pragma unroll
            for (int h = 0; h < 2; h++) {
                int row = rowTile + wm*32 + mt*16 + g4 + h*8;
                size_t off = (size_t)row*HDIM + col;
                float2 y = *(const float2*)&g_Yc[off];
                float v0 = c[h*2], v1 = c[h*2 + 1];
                float z0 = v0 / (1.0f + expf(-v0)) * y.x;
                float z1 = v1 / (1.0f + expf(-v1)) * y.y;
                *(u32*)&g_Zh[off] = pack_f16(z0, z1);
            }
        }
}

// ---------------- output GEMM: out = Z @ Wo ------------------------------------------
__global__ __launch_bounds__(256, 2) void out_mma_kernel(float* __restrict__ out) {
    extern __shared__ __align__(128) char smem[];
    int rowTile = blockIdx.x * 128, ct = blockIdx.y * 128;

    float C[2*8*4] = {};
    mma_mainloop<128>(g_Zh + (size_t)rowTile*HDIM, g_WoT + (size_t)ct*HDIM, smem, C);

    int tid = threadIdx.x, lane = tid & 31, wid = tid >> 5;
    int wm = wid & 3, wn = wid >> 2, g4 = lane >> 2, t4 = lane & 3;

    #pragma unroll
    for (int mt = 0; mt < 2; mt++)
        #pragma unroll
        for (int nt = 0; nt < 8; nt++) {
            const float* c = C + (mt*8 + nt)*4;
            int col = ct + wn*64 + nt*8 + t4*2;
            #pragma unroll
            for (int h = 0; h < 2; h++) {
                int row = rowTile + wm*32 + mt*16 + g4 + h*8;
                *(float2*)&out[(size_t)row*HDIM + col] = make_float2(c[h*2], c[h*2 + 1]);
            }
        }
}

// ---------------- retention: all-fp16 (x2 phase1 + x2 phase2), tile-local decay -----
// smem: Qh [128][72] @0 (18432), Ql @18432; stages @36864, 2 x 18432:
//   per stage: Kh [64][72] @0 (9216), Vth [64][72] @9216.
__global__ __launch_bounds__(256, 2) void ret_mma_kernel(
    const float* __restrict__ gnw, const float* __restrict__ gnb)
{
    extern __shared__ __align__(128) char smem[];
    const int QH = 0, QL = 18432, STG = 36864, SSZ = 18432;
    const int KHo = 0, VHo = 9216;
    u32 sbase = smem_u32(smem);

    int tid = threadIdx.x, lane = tid & 31, wid = tid >> 5;
    int wm = wid & 3, wn = wid >> 2;
    int g4 = lane >> 2, t4 = lane & 3;
    int bx = 7 - (int)blockIdx.x;
    int gbn = blockIdx.y, g = gbn >> 3, bn = gbn & 7;
    int s0 = bx * 128;

    double lgd = log(1.0/32.0) + (double)g * ((log(1.0/512.0) - log(1.0/32.0)) / 7.0);
    float log2g = (float)log2(1.0 - exp(lgd));

    const u16* Qh = g_Qh + ((size_t)gbn*SEQ + s0)*HEAD;
    const u16* Ql = g_Ql + ((size_t)gbn*SEQ + s0)*HEAD;
    const u16* Kh = g_Kh + (size_t)gbn*SEQ*HEAD;
    const u16* Vh = g_Vth + (size_t)gbn*HEAD*SEQ;

    #pragma unroll
    for (int p = 0; p < 4; p++) {
        int lin = p*256 + tid;
        int r = lin >> 3, c16 = lin & 7;
        cp16(sbase + QH + r*144 + c16*16, Qh + (size_t)r*HEAD + c16*8);
        cp16(sbase + QL + r*144 + c16*16, Ql + (size_t)r*HEAD + c16*8);
    }

    auto load_tile = [&](int jt) {
        int t0 = jt * 64;
        u32 sb2 = sbase + STG + (jt & 1)*SSZ;
        #pragma unroll
        for (int p = 0; p < 2; p++) {
            int lin = p*256 + tid;
            int r = lin >> 3, c16 = lin & 7;
            cp16(sb2 + KHo + r*144 + c16*16, Kh + (size_t)(t0 + r)*HEAD + c16*8);
            cp16(sb2 + VHo + r*144 + c16*16, Vh + (size_t)r*SEQ + t0 + c16*8);
        }
        cp_commit();
    };
    load_tile(0);

    int aq = lane >> 3, ar = lane & 7;
    int a_row = wm*32 + ar + (aq & 1)*8;
    int a_kb  = (aq >> 1) * 8;
    int brow4 = ((lane >> 4) & 1)*8 + ar;
    int b_kb4 = ((lane >> 3) & 1) * 8;

    float accY[2*8*4] = {};
    int jtmax = 2*bx + 1;
    for (int jt = 0; jt <= jtmax; jt++) {
        int t0 = jt * 64;
        asm volatile("cp.async.wait_group 0;" ::: "memory");
        __syncthreads();
        if (jt < jtmax) load_tile(jt + 1);

        u32 stg = sbase + STG + (jt & 1)*SSZ;
        u32 sK_h = stg + KHo;
        u32 sV_h = stg + VHo;
        bool diag = (jt >= 2*bx);
        float sc_jt = exp2f((float)(s0 - t0) * log2g);   // residual gamma^(s0 - t0)

        #pragma unroll
        for (int kt = 0; kt < 2; kt++) {
            if (diag && (t0 + wn*32 + kt*16) > (s0 + wm*32 + 31)) continue;

            // phase 1: S = Q'.K'^T (fp16 x2: Qh + Ql against Kh)
            float accS[2][2][4] = {};
            #pragma unroll
            for (int ks = 0; ks < 4; ks++) {
                int k0 = ks * 16;
                u32 ah[2][4], al[2][4];
                #pragma unroll
                for (int mt = 0; mt < 2; mt++) {
                    u32 ao = (u32)((a_row + mt*16)*144 + (k0 + a_kb)*2);
                    ldsm_x4(ah[mt][0], ah[mt][1], ah[mt][2], ah[mt][3], sbase + QH + ao);
                    ldsm_x4(al[mt][0], al[mt][1], al[mt][2], al[mt][3], sbase + QL + ao);
                }
                u32 bo = (u32)((wn*32 + kt*16 + brow4)*144 + (k0 + b_kb4)*2);
                u32 bh[4];
                ldsm_x4(bh[0], bh[1], bh[2], bh[3], sK_h + bo);
                #pragma unroll
                for (int ntp = 0; ntp < 2; ntp++)
                    #pragma unroll
                    for (int mt = 0; mt < 2; mt++) {
                        float* c = accS[mt][ntp];
                        mma_f16(c, ah[mt], bh[ntp*2], bh[ntp*2+1]);
                        mma_f16(c, al[mt], bh[ntp*2], bh[ntp*2+1]);
                    }
            }
            // residual decay scale + mask + pack S to fp16 hi/lo
            u32 sa_h[2][4], sa_l[2][4];
            #pragma unroll
            for (int mt = 0; mt < 2; mt++) {
                #pragma unroll
                for (int ntp = 0; ntp < 2; ntp++) {
                    float* c = accS[mt][ntp];
                    c[0] *= sc_jt; c[1] *= sc_jt; c[2] *= sc_jt; c[3] *= sc_jt;
                    if (diag) {
                        int tb = t0 + wn*32 + kt*16 + ntp*8 + t4*2;
                        int sg0 = s0 + wm*32 + mt*16 + g4;
                        if (tb     > sg0)     c[0] = 0.f;
                        if (tb + 1 > sg0)     c[1] = 0.f;
                        if (tb     > sg0 + 8) c[2] = 0.f;
                        if (tb + 1 > sg0 + 8) c[3] = 0.f;
                    }
                    pack_hilo_f16(c[0], c[1], sa_h[mt][ntp*2],     sa_l[mt][ntp*2]);
                    pack_hilo_f16(c[2], c[3], sa_h[mt][ntp*2 + 1], sa_l[mt][ntp*2 + 1]);
                }
            }
            // phase 2: Y += S.V (fp16 x2: Sh + Sl against Vh)
            #pragma unroll
            for (int ntp2 = 0; ntp2 < 4; ntp2++) {
                u32 bo = (u32)((ntp2*16 + brow4)*144 + (wn*32 + kt*16 + b_kb4)*2);
                u32 bh[4];
                ldsm_x4(bh[0], bh[1], bh[2], bh[3], sV_h + bo);
                #pragma unroll
                for (int sub = 0; sub < 2; sub++) {
                    int nt2 = ntp2*2 + sub;
                    #pragma unroll
                    for (int mt = 0; mt < 2; mt++) {
                        float* c = accY + (mt*8 + nt2)*4;
                        mma_f16(c, sa_h[mt], bh[sub*2], bh[sub*2+1]);
                        mma_f16(c, sa_l[mt], bh[sub*2], bh[sub*2+1]);
                    }
                }
            }
        }
    }

    // cross-warp (wn) Y reduction + group-norm
    __syncthreads();
    float* stage = (float*)smem;   // [128][68]
    if (wn == 0) {
        #pragma unroll
        for (int mt = 0; mt < 2; mt++)
            #pragma unroll
            for (int nt2 = 0; nt2 < 8; nt2++) {
                const float* c = accY + (mt*8 + nt2)*4;
                int col = nt2*8 + t4*2;
                #pragma unroll
                for (int h = 0; h < 2; h++) {
                    int rloc = wm*32 + mt*16 + g4 + h*8;
                    *(float2*)&stage[rloc*68 + col] = make_float2(c[h*2], c[h*2 + 1]);
                }
            }
    }
    __syncthreads();
    if (wn == 1) {
        #pragma unroll
        for (int mt = 0; mt < 2; mt++)
            #pragma unroll
            for (int nt2 = 0; nt2 < 8; nt2++) {
                const float* c = accY + (mt*8 + nt2)*4;
                int col = nt2*8 + t4*2;
                #pragma unroll
                for (int h = 0; h < 2; h++) {
                    int rloc = wm*32 + mt*16 + g4 + h*8;
                    float2 v = *(const float2*)&stage[rloc*68 + col];
                    v.x += c[h*2]; v.y += c[h*2 + 1];
                    *(float2*)&stage[rloc*68 + col] = v;
                }
            }
    }
    __syncthreads();

    float w0 = gnw[g*64 + lane], w1 = gnw[g*64 + lane + 32];
    float b0 = gnb[g*64 + lane], b1 = gnb[g*64 + lane + 32];
    for (int rr = 0; rr < 16; rr++) {
        int row = wid*16 + rr;
        float v0 = stage[row*68 + lane], v1 = stage[row*68 + lane + 32];
        float sum = v0 + v1;
        #pragma unroll
        for (int off = 16; off; off >>= 1) sum += __shfl_xor_sync(0xffffffffu, sum, off);
        float mean = sum * 0.015625f;
        float d0 = v0 - mean, d1 = v1 - mean;
        float sq = d0*d0 + d1*d1;
        #pragma unroll
        for (int off = 16; off; off >>= 1) sq += __shfl_xor_sync(0xffffffffu, sq, off);
        float rstd = rsqrtf(sq * 0.015625f + EPSV);
        float* dst = g_Yc + ((size_t)(bn*SEQ + s0 + row))*HDIM + g*64;
        dst[lane]      = d0 * rstd * w0 + b0;
        dst[lane + 32] = d1 * rstd * w1 + b1;
    }
}

// ---------------- launch -------------------------------------------------------------
extern "C" void kernel_launch(void* const* d_in, const int* in_sizes, int n_in,
                              void* d_out, int out_size)
{
    (void)in_sizes; (void)n_in; (void)out_size;
    const float* X   = (const float*)d_in[0];
    const float* Wq  = (const float*)d_in[1];
    const float* Wk  = (const float*)d_in[2];
    const float* Wv  = (const float*)d_in[3];
    const float* Wg  = (const float*)d_in[4];
    const float* Wo  = (const float*)d_in[5];
    const float* gnw = (const float*)d_in[6];
    const float* gnb = (const float*)d_in[7];
    float* out = (float*)d_out;

    const int RET_SMEM  = 36864 + 2*18432;   // 73728
    const int SMEM_QKV  = 2 * 25600;         // 51200
    const int SMEM_128  = 2 * 20480;         // 40960
    cudaFuncSetAttribute(ret_mma_kernel, cudaFuncAttributeMaxDynamicSharedMemorySize, RET_SMEM);
    cudaFuncSetAttribute(qkv_mma_kernel, cudaFuncAttributeMaxDynamicSharedMemorySize, SMEM_QKV);
    cudaFuncSetAttribute(gate_mma_kernel, cudaFuncAttributeMaxDynamicSharedMemorySize, SMEM_128);
    cudaFuncSetAttribute(out_mma_kernel, cudaFuncAttributeMaxDynamicSharedMemorySize, SMEM_128);

    tables_kernel<<<128, 256>>>();
    convX_kernel<<<NROWS*HDIM/4/256, 256>>>(X);
    convW_all<<<5120, 256>>>(Wq, Wk, Wv, Wg, Wo);
    qkv_mma_kernel<<<dim3(64, 8), 256, SMEM_QKV>>>();
    ret_mma_kernel<<<dim3(8, 64), 256, RET_SMEM>>>(gnw, gnb);
    gate_mma_kernel<<<dim3(64, 4), 256, SMEM_128>>>();
    out_mma_kernel<<<dim3(64, 4), 256, SMEM_128>>>(out);
}

// round 14
// speedup vs baseline: 1.2060x; 1.1358x over previous
#include <cuda_runtime.h>
#include <cuda_bf16.h>
#include <cuda_fp16.h>
#include <math.h>
#include <stdint.h>

#define SEQ   1024
#define HEAD  64
#define HDIM  512
#define BN    8
#define NROWS (BN*SEQ)
#define EPSV  1e-5f

typedef unsigned long long u64;
typedef unsigned int u32;
typedef unsigned short u16;

// ---------------- scratch (device globals; allocation-free rule) ----------------
__device__ __align__(256) float g_sin[SEQ*32];
__device__ __align__(256) float g_cos[SEQ*32];
__device__ __align__(256) float g_scl[SEQ*32];
__device__ __align__(256) float g_Yc[NROWS*HDIM];
// fp16 operands (projection GEMMs, hi only)
__device__ __align__(256) u16 g_Xh[NROWS*HDIM];
__device__ __align__(256) u16 g_Zh[NROWS*HDIM];
__device__ __align__(256) u16 g_WgT[HDIM*HDIM];
__device__ __align__(256) u16 g_WoT[HDIM*HDIM];
__device__ __align__(256) u16 g_WqkvT[3*8*HEAD*HDIM];
// retention operands, fp16 (hi only), tile-local decay fold:
//   Q' = Q rot sc  gamma^(s mod 128);  K' = K rot /sc gamma^-(t mod 64);  V^T [d][t]
__device__ __align__(256) u16 g_Qh[8*BN*SEQ*HEAD];
__device__ __align__(256) u16 g_Kh[8*BN*SEQ*HEAD];
__device__ __align__(256) u16 g_Vth[8*BN*HEAD*SEQ];

// ---------------- helpers ----------------------------------------------------------
__device__ __forceinline__ u32 smem_u32(const void* p) {
    u32 a;
    asm("{ .reg .u64 t; cvta.to.shared.u64 t, %1; cvt.u32.u64 %0, t; }" : "=r"(a) : "l"(p));
    return a;
}
__device__ __forceinline__ void ldsm_x4(u32& r0, u32& r1, u32& r2, u32& r3, u32 addr) {
    asm volatile("ldmatrix.sync.aligned.m8n8.x4.shared.b16 {%0,%1,%2,%3}, [%4];"
        : "=r"(r0), "=r"(r1), "=r"(r2), "=r"(r3) : "r"(addr));
}
__device__ __forceinline__ void mma_f16(float* c, const u32* a, u32 b0, u32 b1) {
    asm volatile("mma.sync.aligned.m16n8k16.row.col.f32.f16.f16.f32 "
        "{%0,%1,%2,%3}, {%4,%5,%6,%7}, {%8,%9}, {%0,%1,%2,%3};"
        : "+f"(c[0]), "+f"(c[1]), "+f"(c[2]), "+f"(c[3])
        : "r"(a[0]), "r"(a[1]), "r"(a[2]), "r"(a[3]), "r"(b0), "r"(b1));
}
__device__ __forceinline__ u32 pack_f16(float c0, float c1) {
    __half2 h2 = __floats2half2_rn(c0, c1);
    return *(u32*)&h2;
}
__device__ __forceinline__ void cp16(u32 saddr, const void* g) {
    asm volatile("cp.async.cg.shared.global [%0], [%1], 16;" :: "r"(saddr), "l"(g));
}
__device__ __forceinline__ void cp_commit() {
    asm volatile("cp.async.commit_group;" ::: "memory");
}

// ---------------- xpos tables in fp64 ---------------------------------------------
__global__ void tables_kernel() {
    int idx = blockIdx.x * blockDim.x + threadIdx.x;
    if (idx >= SEQ * 32) return;
    int s = idx >> 5, j = idx & 31;
    double inv_freq = pow(10000.0, -(double)j / 32.0);
    double ang = (double)s * inv_freq;
    g_sin[idx] = (float)sin(ang);
    g_cos[idx] = (float)cos(ang);
    double sv = (2.0 * j + 25.6) / 89.6;
    g_scl[idx] = (float)pow(sv, (double)s / 512.0);
}

// ---------------- converters -------------------------------------------------------
__global__ __launch_bounds__(256) void convX_kernel(const float* __restrict__ X) {
    int i = blockIdx.x * 256 + threadIdx.x;
    float4 v = ((const float4*)X)[i];
    ((uint2*)g_Xh)[i] = make_uint2(pack_f16(v.x, v.y), pack_f16(v.z, v.w));
}
__global__ __launch_bounds__(256) void convW_all(
    const float* __restrict__ Wq, const float* __restrict__ Wk, const float* __restrict__ Wv,
    const float* __restrict__ Wg, const float* __restrict__ Wo) {
    int i = blockIdx.x * 256 + threadIdx.x;
    if (i < 524288) {
        int which = i >> 18;
        int j = i & 262143;
        int n = j >> 9, k = j & 511;
        const float* W = which ? Wo : Wg;
        u16 h = __half_as_ushort(__float2half_rn(W[(size_t)k * HDIM + n]));
        (which ? g_WoT : g_WgT)[j] = h;
    } else {
        int j = i - 524288;
        int k = j & 511, n = (j >> 9) & 63, g = (j >> 15) & 7, mat = j >> 18;
        const float* W = (mat == 0 ? Wq : (mat == 1 ? Wk : Wv));
        g_WqkvT[j] = __half_as_ushort(__float2half_rn(
            W[(size_t)g * HDIM * HEAD + (size_t)k * HEAD + n]));
    }
}

// ---------------- pure-fp16 mainloop (gate/out): cp.async 2-stage, K=32 -------------
#define PITCH 40

template<int BROWS>
__device__ __forceinline__ void mma_mainloop(
    const u16* __restrict__ Ah, const u16* __restrict__ Bh, char* smem, float* C)
{
    constexpr int NTI   = BROWS / 16;
    constexpr int ABYT  = 128 * PITCH * 2;
    constexpr int BBYT  = BROWS * PITCH * 2;
    constexpr int STAGE = ABYT + BBYT;
    constexpr int AGRAN = 128 * 4;
    constexpr int BGRAN = BROWS * 4;
    constexpr int NG    = (AGRAN + BGRAN) / 256;

    int tid = threadIdx.x, lane = tid & 31, wid = tid >> 5;
    int wm = wid & 3, wn = wid >> 2;
    u32 sbase = smem_u32(smem);

    int garr[NG], grow[NG], gc16[NG];
    #pragma unroll
    for (int i = 0; i < NG; i++) {
        int g = i * 256 + tid;
        int arr = (g < AGRAN) ? 0 : 1;
        int rem = (g < AGRAN) ? g : g - AGRAN;
        garr[i] = arr; grow[i] = rem >> 2; gc16[i] = rem & 3;
    }
    const u16* srcs[2] = {Ah, Bh};
    const int offs[2] = {0, ABYT};

    auto issue = [&](int ch) {
        int st = ch & 1;
        int kk = ch * 32;
        #pragma unroll
        for (int i = 0; i < NG; i++)
            cp16(sbase + st*STAGE + offs[garr[i]] + grow[i]*(PITCH*2) + gc16[i]*16,
                 srcs[garr[i]] + (size_t)grow[i]*HDIM + kk + gc16[i]*8);
        cp_commit();
    };

    int aq = lane >> 3, ar = lane & 7;
    int a_row = wm*32 + ar + (aq & 1)*8;
    int a_kb  = (aq >> 1) * 8;
    int b_row4 = wn*(BROWS/2) + ((lane >> 4) & 1)*8 + ar;
    int b_kb4  = ((lane >> 3) & 1) * 8;

    issue(0);
    #pragma unroll 1
    for (int ch = 0; ch < 16; ch++) {
        asm volatile("cp.async.wait_group 0;" ::: "memory");
        __syncthreads();
        if (ch < 15) issue(ch + 1);
        int st = ch & 1;
        u32 sA_h = sbase + st*STAGE;
        u32 sB_h = sA_h + ABYT;
        #pragma unroll
        for (int ks = 0; ks < 2; ks++) {
            int k0 = ks * 16;
            u32 ah[2][4];
            #pragma unroll
            for (int mt = 0; mt < 2; mt++) {
                u32 ao = (u32)((a_row + mt*16) * (PITCH*2) + (k0 + a_kb) * 2);
                ldsm_x4(ah[mt][0], ah[mt][1], ah[mt][2], ah[mt][3], sA_h + ao);
            }
            #pragma unroll
            for (int ntp = 0; ntp < NTI/2; ntp++) {
                u32 bo = (u32)((b_row4 + ntp*16) * (PITCH*2) + (k0 + b_kb4) * 2);
                u32 bh[4];
                ldsm_x4(bh[0], bh[1], bh[2], bh[3], sB_h + bo);
                #pragma unroll
                for (int sub = 0; sub < 2; sub++) {
                    int nt = ntp*2 + sub;
                    #pragma unroll
                    for (int mt = 0; mt < 2; mt++)
                        mma_f16(C + (mt*NTI + nt)*4, ah[mt], bh[sub*2], bh[sub*2+1]);
                }
            }
        }
    }
}

// ---------------- QKV GEMM (merged NT=192, pure fp16, K=32, 2-stage) ----------------
__global__ __launch_bounds__(256, 2) void qkv_mma_kernel() {
    extern __shared__ __align__(128) char smem[];
    const int ABYT = 10240, STAGE = 25600;
    const int offs[2] = {0, ABYT};
    u32 sbase = smem_u32(smem);

    int tid = threadIdx.x, lane = tid & 31, wid = tid >> 5;
    int wm = wid & 3, wn = wid >> 2;
    int g4 = lane >> 2, t4 = lane & 3;
    int rowTile = blockIdx.x * 128;
    int g = blockIdx.y;

    const u16* Ah = g_Xh + (size_t)rowTile*HDIM;
    const u16* srcs[2] = {Ah, g_WqkvT};

    int garr[5], grow[5], gc16[5], gsrow[5];
    #pragma unroll
    for (int i = 0; i < 5; i++) {
        int gg = i * 256 + tid;
        int arr = (gg < 512) ? 0 : 1;
        int rem = (gg < 512) ? gg : gg - 512;
        garr[i] = arr; grow[i] = rem >> 2; gc16[i] = rem & 3;
        gsrow[i] = (arr == 0) ? grow[i] : ((grow[i] >> 6)*512 + g*64 + (grow[i] & 63));
    }
    auto issue = [&](int ch) {
        int st = ch & 1;
        u32 db = sbase + st*STAGE;
        int kk = ch * 32;
        #pragma unroll
        for (int i = 0; i < 5; i++)
            cp16(db + offs[garr[i]] + grow[i]*(PITCH*2) + gc16[i]*16,
                 srcs[garr[i]] + (size_t)gsrow[i]*HDIM + kk + gc16[i]*8);
        cp_commit();
    };

    int aq = lane >> 3, ar = lane & 7;
    int a_row = wm*32 + ar + (aq & 1)*8;
    int a_kb  = (aq >> 1) * 8;
    int b_row4 = wn*96 + ((lane >> 4) & 1)*8 + ar;
    int b_kb4  = ((lane >> 3) & 1) * 8;

    float C[2*12*4] = {};

    issue(0);
    #pragma unroll 1
    for (int ch = 0; ch < 16; ch++) {
        asm volatile("cp.async.wait_group 0;" ::: "memory");
        __syncthreads();
        if (ch < 15) issue(ch + 1);
        int st = ch & 1;
        u32 sA_h = sbase + st*STAGE;
        u32 sB_h = sA_h + ABYT;
        #pragma unroll
        for (int ks = 0; ks < 2; ks++) {
            int k0 = ks * 16;
            u32 ah[2][4];
            #pragma unroll
            for (int mt = 0; mt < 2; mt++) {
                u32 ao = (u32)((a_row + mt*16) * (PITCH*2) + (k0 + a_kb) * 2);
                ldsm_x4(ah[mt][0], ah[mt][1], ah[mt][2], ah[mt][3], sA_h + ao);
            }
            #pragma unroll
            for (int ntp = 0; ntp < 6; ntp++) {
                u32 bo = (u32)((b_row4 + ntp*16) * (PITCH*2) + (k0 + b_kb4) * 2);
                u32 bh[4];
                ldsm_x4(bh[0], bh[1], bh[2], bh[3], sB_h + bo);
                #pragma unroll
                for (int sub = 0; sub < 2; sub++) {
                    int nt = ntp*2 + sub;
                    #pragma unroll
                    for (int mt = 0; mt < 2; mt++)
                        mma_f16(C + (mt*12 + nt)*4, ah[mt], bh[sub*2], bh[sub*2+1]);
                }
            }
        }
    }

    // ---- epilogue: rotary/xpos + tile-local decay fold, fp16 outputs ----
    int bn = rowTile >> 10, sb = rowTile & 1023;   // sb is 128-aligned
    size_t gbn = (size_t)(g*8 + bn);

    double lgd = log(1.0/32.0) + (double)g * ((log(1.0/512.0) - log(1.0/32.0)) / 7.0);
    float log2g = (float)log2(1.0 - exp(lgd));
    float fdq[2][2], fdk[2][2];
    #pragma unroll
    for (int mt = 0; mt < 2; mt++)
        #pragma unroll
        for (int h = 0; h < 2; h++) {
            int rloc = wm*32 + mt*16 + g4 + h*8;
            fdq[mt][h] = exp2f((float)rloc * log2g);          // gamma^(s mod 128)
            fdk[mt][h] = exp2f(-(float)(rloc & 63) * log2g);  // gamma^-(t mod 64)
        }

    __syncthreads();
    u16* sVh = (u16*)smem;       // [64][136]

    #pragma unroll
    for (int nt = 0; nt < 12; nt++) {
        int col192 = wn*96 + nt*8 + t4*2;
        int mat = col192 >> 6, col = col192 & 63;
        #pragma unroll
        for (int mt = 0; mt < 2; mt++) {
            const float* c = C + (mt*12 + nt)*4;
            #pragma unroll
            for (int h = 0; h < 2; h++) {
                int rloc = wm*32 + mt*16 + g4 + h*8;
                int s = sb + rloc;
                float e = c[h*2], o = c[h*2 + 1];
                if (mat == 2) {
                    sVh[col*136 + rloc]     = __half_as_ushort(__float2half_rn(e));
                    sVh[(col+1)*136 + rloc] = __half_as_ushort(__float2half_rn(o));
                } else {
                    int j2 = col >> 1;
                    float sn = g_sin[s*32 + j2], cs = g_cos[s*32 + j2], sc = g_scl[s*32 + j2];
                    float re = e*cs - o*sn;
                    float ro = o*cs + e*sn;
                    size_t off = (gbn*SEQ + s)*HEAD + col;
                    if (mat == 0) {
                        float m = sc * fdq[mt][h];
                        *(u32*)&g_Qh[off] = pack_f16(re*m, ro*m);
                    } else {
                        float m = (1.0f/sc) * fdk[mt][h];
                        *(u32*)&g_Kh[off] = pack_f16(re*m, ro*m);
                    }
                }
            }
        }
    }
    __syncthreads();
    #pragma unroll
    for (int p = 0; p < 4; p++) {
        int lin = p*256 + tid;
        int d = lin >> 4, c16 = lin & 15;
        *(uint4*)&g_Vth[(gbn*HEAD + d)*SEQ + sb + c16*8] = *(const uint4*)&sVh[d*136 + c16*8];
    }
}

// ---------------- gate GEMM: Z = silu(X@Wg)*Yc -> fp16 ------------------------------
__global__ __launch_bounds__(256, 2) void gate_mma_kernel() {
    extern __shared__ __align__(128) char smem[];
    int rowTile = blockIdx.x * 128, ct = blockIdx.y * 128;

    float C[2*8*4] = {};
    mma_mainloop<128>(g_Xh + (size_t)rowTile*HDIM, g_WgT + (size_t)ct*HDIM, smem, C);

    int tid = threadIdx.x, lane = tid & 31, wid = tid >> 5;
    int wm = wid & 3, wn = wid >> 2, g4 = lane >> 2, t4 = lane & 3;

    #pragma unroll
    for (int mt = 0; mt < 2; mt++)
        #pragma unroll
        for (int nt = 0; nt < 8; nt++) {
            const float* c = C + (mt*8 + nt)*4;
            int col = ct + wn*64 + nt*8 + t4*2;
            #pragma unroll
            for (int h = 0; h < 2; h++) {
                int row = rowTile + wm*32 + mt*16 + g4 + h*8;
                size_t off = (size_t)row*HDIM + col;
                float2 y = *(const float2*)&g_Yc[off];
                float v0 = c[h*2], v1 = c[h*2 + 1];
                float z0 = v0 / (1.0f + expf(-v0)) * y.x;
                float z1 = v1 / (1.0f + expf(-v1)) * y.y;
                *(u32*)&g_Zh[off] = pack_f16(z0, z1);
            }
        }
}

// ---------------- output GEMM: out = Z @ Wo ------------------------------------------
__global__ __launch_bounds__(256, 2) void out_mma_kernel(float* __restrict__ out) {
    extern __shared__ __align__(128) char smem[];
    int rowTile = blockIdx.x * 128, ct = blockIdx.y * 128;

    float C[2*8*4] = {};
    mma_mainloop<128>(g_Zh + (size_t)rowTile*HDIM, g_WoT + (size_t)ct*HDIM, smem, C);

    int tid = threadIdx.x, lane = tid & 31, wid = tid >> 5;
    int wm = wid & 3, wn = wid >> 2, g4 = lane >> 2, t4 = lane & 3;

    #pragma unroll
    for (int mt = 0; mt < 2; mt++)
        #pragma unroll
        for (int nt = 0; nt < 8; nt++) {
            const float* c = C + (mt*8 + nt)*4;
            int col = ct + wn*64 + nt*8 + t4*2;
            #pragma unroll
            for (int h = 0; h < 2; h++) {
                int row = rowTile + wm*32 + mt*16 + g4 + h*8;
                *(float2*)&out[(size_t)row*HDIM + col] = make_float2(c[h*2], c[h*2 + 1]);
            }
        }
}

// ---------------- retention: all-fp16 single (1 MMA phase1 + 1 MMA phase2) ----------
// smem: Qh [128][72] @0 (18432); stages @18432, 2 x 18432:
//   per stage: Kh [64][72] @0 (9216), Vth [64][72] @9216.
__global__ __launch_bounds__(256, 2) void ret_mma_kernel(
    const float* __restrict__ gnw, const float* __restrict__ gnb)
{
    extern __shared__ __align__(128) char smem[];
    const int QH = 0, STG = 18432, SSZ = 18432;
    const int KHo = 0, VHo = 9216;
    u32 sbase = smem_u32(smem);

    int tid = threadIdx.x, lane = tid & 31, wid = tid >> 5;
    int wm = wid & 3, wn = wid >> 2;
    int g4 = lane >> 2, t4 = lane & 3;
    int bx = 7 - (int)blockIdx.x;
    int gbn = blockIdx.y, g = gbn >> 3, bn = gbn & 7;
    int s0 = bx * 128;

    double lgd = log(1.0/32.0) + (double)g * ((log(1.0/512.0) - log(1.0/32.0)) / 7.0);
    float log2g = (float)log2(1.0 - exp(lgd));

    const u16* Qh = g_Qh + ((size_t)gbn*SEQ + s0)*HEAD;
    const u16* Kh = g_Kh + (size_t)gbn*SEQ*HEAD;
    const u16* Vh = g_Vth + (size_t)gbn*HEAD*SEQ;

    #pragma unroll
    for (int p = 0; p < 4; p++) {
        int lin = p*256 + tid;
        int r = lin >> 3, c16 = lin & 7;
        cp16(sbase + QH + r*144 + c16*16, Qh + (size_t)r*HEAD + c16*8);
    }

    auto load_tile = [&](int jt) {
        int t0 = jt * 64;
        u32 sb2 = sbase + STG + (jt & 1)*SSZ;
        #pragma unroll
        for (int p = 0; p < 2; p++) {
            int lin = p*256 + tid;
            int r = lin >> 3, c16 = lin & 7;
            cp16(sb2 + KHo + r*144 + c16*16, Kh + (size_t)(t0 + r)*HEAD + c16*8);
            cp16(sb2 + VHo + r*144 + c16*16, Vh + (size_t)r*SEQ + t0 + c16*8);
        }
        cp_commit();
    };
    load_tile(0);

    int aq = lane >> 3, ar = lane & 7;
    int a_row = wm*32 + ar + (aq & 1)*8;
    int a_kb  = (aq >> 1) * 8;
    int brow4 = ((lane >> 4) & 1)*8 + ar;
    int b_kb4 = ((lane >> 3) & 1) * 8;

    float accY[2*8*4] = {};
    int jtmax = 2*bx + 1;
    for (int jt = 0; jt <= jtmax; jt++) {
        int t0 = jt * 64;
        asm volatile("cp.async.wait_group 0;" ::: "memory");
        __syncthreads();
        if (jt < jtmax) load_tile(jt + 1);

        u32 stg = sbase + STG + (jt & 1)*SSZ;
        u32 sK_h = stg + KHo;
        u32 sV_h = stg + VHo;
        bool diag = (jt >= 2*bx);
        float sc_jt = exp2f((float)(s0 - t0) * log2g);   // residual gamma^(s0 - t0)

        #pragma unroll
        for (int kt = 0; kt < 2; kt++) {
            if (diag && (t0 + wn*32 + kt*16) > (s0 + wm*32 + 31)) continue;

            // phase 1: S = Q'.K'^T (fp16, single)
            float accS[2][2][4] = {};
            #pragma unroll
            for (int ks = 0; ks < 4; ks++) {
                int k0 = ks * 16;
                u32 ah[2][4];
                #pragma unroll
                for (int mt = 0; mt < 2; mt++) {
                    u32 ao = (u32)((a_row + mt*16)*144 + (k0 + a_kb)*2);
                    ldsm_x4(ah[mt][0], ah[mt][1], ah[mt][2], ah[mt][3], sbase + QH + ao);
                }
                u32 bo = (u32)((wn*32 + kt*16 + brow4)*144 + (k0 + b_kb4)*2);
                u32 bh[4];
                ldsm_x4(bh[0], bh[1], bh[2], bh[3], sK_h + bo);
                #pragma unroll
                for (int ntp = 0; ntp < 2; ntp++)
                    #pragma unroll
                    for (int mt = 0; mt < 2; mt++)
                        mma_f16(accS[mt][ntp], ah[mt], bh[ntp*2], bh[ntp*2+1]);
            }
            // residual decay scale + mask + pack S to fp16 (single)
            u32 sa[2][4];
            #pragma unroll
            for (int mt = 0; mt < 2; mt++) {
                #pragma unroll
                for (int ntp = 0; ntp < 2; ntp++) {
                    float* c = accS[mt][ntp];
                    c[0] *= sc_jt; c[1] *= sc_jt; c[2] *= sc_jt; c[3] *= sc_jt;
                    if (diag) {
                        int tb = t0 + wn*32 + kt*16 + ntp*8 + t4*2;
                        int sg0 = s0 + wm*32 + mt*16 + g4;
                        if (tb     > sg0)     c[0] = 0.f;
                        if (tb + 1 > sg0)     c[1] = 0.f;
                        if (tb     > sg0 + 8) c[2] = 0.f;
                        if (tb + 1 > sg0 + 8) c[3] = 0.f;
                    }
                    sa[mt][ntp*2]     = pack_f16(c[0], c[1]);
                    sa[mt][ntp*2 + 1] = pack_f16(c[2], c[3]);
                }
            }
            // phase 2: Y += S.V (fp16, single)
            #pragma unroll
            for (int ntp2 = 0; ntp2 < 4; ntp2++) {
                u32 bo = (u32)((ntp2*16 + brow4)*144 + (wn*32 + kt*16 + b_kb4)*2);
                u32 bh[4];
                ldsm_x4(bh[0], bh[1], bh[2], bh[3], sV_h + bo);
                #pragma unroll
                for (int sub = 0; sub < 2; sub++) {
                    int nt2 = ntp2*2 + sub;
                    #pragma unroll
                    for (int mt = 0; mt < 2; mt++)
                        mma_f16(accY + (mt*8 + nt2)*4, sa[mt], bh[sub*2], bh[sub*2+1]);
                }
            }
        }
    }

    // cross-warp (wn) Y reduction + group-norm
    __syncthreads();
    float* stage = (float*)smem;   // [128][68]
    if (wn == 0) {
        #pragma unroll
        for (int mt = 0; mt < 2; mt++)
            #pragma unroll
            for (int nt2 = 0; nt2 < 8; nt2++) {
                const float* c = accY + (mt*8 + nt2)*4;
                int col = nt2*8 + t4*2;
                #pragma unroll
                for (int h = 0; h < 2; h++) {
                    int rloc = wm*32 + mt*16 + g4 + h*8;
                    *(float2*)&stage[rloc*68 + col] = make_float2(c[h*2], c[h*2 + 1]);
                }
            }
    }
    __syncthreads();
    if (wn == 1) {
        #pragma unroll
        for (int mt = 0; mt < 2; mt++)
            #pragma unroll
            for (int nt2 = 0; nt2 < 8; nt2++) {
                const float* c = accY + (mt*8 + nt2)*4;
                int col = nt2*8 + t4*2;
                #pragma unroll
                for (int h = 0; h < 2; h++) {
                    int rloc = wm*32 + mt*16 + g4 + h*8;
                    float2 v = *(const float2*)&stage[rloc*68 + col];
                    v.x += c[h*2]; v.y += c[h*2 + 1];
                    *(float2*)&stage[rloc*68 + col] = v;
                }
            }
    }
    __syncthreads();

    float w0 = gnw[g*64 + lane], w1 = gnw[g*64 + lane + 32];
    float b0 = gnb[g*64 + lane], b1 = gnb[g*64 + lane + 32];
    for (int rr = 0; rr < 16; rr++) {
        int row = wid*16 + rr;
        float v0 = stage[row*68 + lane], v1 = stage[row*68 + lane + 32];
        float sum = v0 + v1;
        #pragma unroll
        for (int off = 16; off; off >>= 1) sum += __shfl_xor_sync(0xffffffffu, sum, off);
        float mean = sum * 0.015625f;
        float d0 = v0 - mean, d1 = v1 - mean;
        float sq = d0*d0 + d1*d1;
        #pragma unroll
        for (int off = 16; off; off >>= 1) sq += __shfl_xor_sync(0xffffffffu, sq, off);
        float rstd = rsqrtf(sq * 0.015625f + EPSV);
        float* dst = g_Yc + ((size_t)(bn*SEQ + s0 + row))*HDIM + g*64;
        dst[lane]      = d0 * rstd * w0 + b0;
        dst[lane + 32] = d1 * rstd * w1 + b1;
    }
}

// ---------------- launch -------------------------------------------------------------
extern "C" void kernel_launch(void* const* d_in, const int* in_sizes, int n_in,
                              void* d_out, int out_size)
{
    (void)in_sizes; (void)n_in; (void)out_size;
    const float* X   = (const float*)d_in[0];
    const float* Wq  = (const float*)d_in[1];
    const float* Wk  = (const float*)d_in[2];
    const float* Wv  = (const float*)d_in[3];
    const float* Wg  = (const float*)d_in[4];
    const float* Wo  = (const float*)d_in[5];
    const float* gnw = (const float*)d_in[6];
    const float* gnb = (const float*)d_in[7];
    float* out = (float*)d_out;

    const int RET_SMEM  = 18432 + 2*18432;   // 55296
    const int SMEM_QKV  = 2 * 25600;         // 51200
    const int SMEM_128  = 2 * 20480;         // 40960
    cudaFuncSetAttribute(ret_mma_kernel, cudaFuncAttributeMaxDynamicSharedMemorySize, RET_SMEM);
    cudaFuncSetAttribute(qkv_mma_kernel, cudaFuncAttributeMaxDynamicSharedMemorySize, SMEM_QKV);
    cudaFuncSetAttribute(gate_mma_kernel, cudaFuncAttributeMaxDynamicSharedMemorySize, SMEM_128);
    cudaFuncSetAttribute(out_mma_kernel, cudaFuncAttributeMaxDynamicSharedMemorySize, SMEM_128);

    tables_kernel<<<128, 256>>>();
    convX_kernel<<<NROWS*HDIM/4/256, 256>>>(X);
    convW_all<<<5120, 256>>>(Wq, Wk, Wv, Wg, Wo);
    qkv_mma_kernel<<<dim3(64, 8), 256, SMEM_QKV>>>();
    ret_mma_kernel<<<dim3(8, 64), 256, RET_SMEM>>>(gnw, gnb);
    gate_mma_kernel<<<dim3(64, 4), 256, SMEM_128>>>();
    out_mma_kernel<<<dim3(64, 4), 256, SMEM_128>>>(out);
}